// round 16
// baseline (speedup 1.0000x reference)
#include <cuda_runtime.h>
#include <cuda_bf16.h>
#include <math.h>
#include <cstdint>

#define BB   4
#define CH   128
#define HH   240
#define WW   320
#define NK   4000
#define NPOS 8
#define KSZ  3
#define HWSZ (HH*WW)
#define MAXOFF 80.0f

#define NKP_TOT (BB*NK)          // 16000
#define MROWS   (NKP_TOT*NPOS)   // 128000

// ---------------- scratch (static device globals; no runtime alloc) ------------
__device__ __align__(16) float g_xT[(size_t)BB*HWSZ*CH];        // NHWC
__device__ __align__(16) float2 g_pos[(size_t)MROWS];           // sample positions (px,py)
__device__ __align__(256) __nv_bfloat16 g_fhi[(size_t)MROWS*CH];
__device__ __align__(256) __nv_bfloat16 g_flo[(size_t)MROWS*CH];
__device__ __align__(256) __nv_bfloat16 g_sfw_hi[CH*CH];        // [d][c]
__device__ __align__(256) __nv_bfloat16 g_sfw_lo[CH*CH];
__device__ __align__(256) __nv_bfloat16 g_agg_hi[NPOS*CH*CH];   // [p][D][c']
__device__ __align__(256) __nv_bfloat16 g_agg_lo[NPOS*CH*CH];
__device__ __align__(16) float g_part[2][(size_t)NKP_TOT*CH];   // split-K partials

// ================= warp-MMA helpers (HMMA path, works on plain sm_103) ==========
__device__ __forceinline__ uint32_t smem_u32(const void* p) {
    return (uint32_t)__cvta_generic_to_shared(p);
}
__device__ __forceinline__ void ldsm4(uint32_t r[4], uint32_t addr) {
    asm volatile("ldmatrix.sync.aligned.m8n8.x4.shared.b16 {%0,%1,%2,%3}, [%4];"
                 : "=r"(r[0]), "=r"(r[1]), "=r"(r[2]), "=r"(r[3]) : "r"(addr));
}
__device__ __forceinline__ void mma16816(float d[4], const uint32_t a[4], const uint32_t b[2]) {
    asm volatile("mma.sync.aligned.m16n8k16.row.col.f32.bf16.bf16.f32 "
                 "{%0,%1,%2,%3}, {%4,%5,%6,%7}, {%8,%9}, {%0,%1,%2,%3};"
                 : "+f"(d[0]), "+f"(d[1]), "+f"(d[2]), "+f"(d[3])
                 : "r"(a[0]), "r"(a[1]), "r"(a[2]), "r"(a[3]), "r"(b[0]), "r"(b[1]));
}
__device__ __forceinline__ uint32_t pack2bf(float a, float b) {
    __nv_bfloat162 t = __floats2bfloat162_rn(a, b);
    return *(uint32_t*)&t;
}
// 16B-chunk XOR swizzles: 256B rows (16 chunks) and 128B rows (8 chunks)
#define SW_OFF(row, chunk) ((uint32_t)(row) * 256u + ((uint32_t)((chunk) ^ ((row) & 7)) << 4))
#define SW8_OFF(row, chunk) ((uint32_t)(row) * 128u + ((uint32_t)((chunk) ^ ((row) & 7)) << 4))

#define CP_ASYNC16(dst, src) \
    asm volatile("cp.async.cg.shared.global [%0], [%1], 16;" :: "r"(dst), "l"(src))
#define CP_COMMIT() asm volatile("cp.async.commit_group;" ::: "memory")
#define CP_WAIT(n)  asm volatile("cp.async.wait_group %0;" :: "n"(n) : "memory")

// ---------------- K1: NCHW -> NHWC transpose ------------------------------------
__global__ void k_transpose(const float* __restrict__ x) {
    __shared__ float tile[32][33];
    int b  = blockIdx.z;
    int c0 = blockIdx.y * 32;
    int hw0 = blockIdx.x * 32;
    int tx = threadIdx.x, ty = threadIdx.y;     // 32 x 8
    const float* xb = x + (size_t)b * CH * HWSZ;
    #pragma unroll
    for (int i = ty; i < 32; i += 8)
        tile[i][tx] = xb[(size_t)(c0 + i) * HWSZ + hw0 + tx];
    __syncthreads();
    float* ob = g_xT + (size_t)b * HWSZ * CH;
    #pragma unroll
    for (int i = ty; i < 32; i += 8)
        ob[(size_t)(hw0 + i) * CH + c0 + tx] = tile[tx][i];
}

// ---------------- merged prep: agg transpose-split (z<NPOS) + sfw split (z==NPOS)
__global__ void k_prep(const float* __restrict__ agg, const float* __restrict__ sfw) {
    __shared__ float t[32][33];
    int p  = blockIdx.z;
    int tx = threadIdx.x, ty = threadIdx.y;     // 32 x 8
    if (p == NPOS) {
        int c0 = blockIdx.x * 32;
        int d0 = blockIdx.y * 32;
        #pragma unroll
        for (int i = ty; i < 32; i += 8) {
            int idx = (d0 + i) * CH + c0 + tx;
            float v = sfw[idx];
            __nv_bfloat16 h = __float2bfloat16(v);
            g_sfw_hi[idx] = h;
            g_sfw_lo[idx] = __float2bfloat16(v - __bfloat162float(h));
        }
        return;
    }
    int c0 = blockIdx.x * 32;
    int d0 = blockIdx.y * 32;
    const float* src = agg + (size_t)p * CH * CH;
    #pragma unroll
    for (int i = ty; i < 32; i += 8)
        t[i][tx] = src[(size_t)(c0 + i) * CH + d0 + tx];
    __syncthreads();
    #pragma unroll
    for (int i = ty; i < 32; i += 8) {
        float v = t[tx][i];
        __nv_bfloat16 h = __float2bfloat16(v);
        size_t oi = (size_t)p * CH * CH + (size_t)(d0 + i) * CH + c0 + tx;
        g_agg_hi[oi] = h;
        g_agg_lo[oi] = __float2bfloat16(v - __bfloat162float(h));
    }
}

// ---------------- K2a: 2-kp-per-warp offset MLP, 512 thr = 32 kp/block ----------
__global__ __launch_bounds__(512) void k_off(
        const float* __restrict__ kpts,
        const float* __restrict__ w1, const float* __restrict__ b1,
        const float* __restrict__ w2, const float* __restrict__ b2) {
    extern __shared__ float w1s[];            // [16][9][128]
    __shared__ float b1s[16];

    int tid = threadIdx.x;
    for (int idx = tid; idx < 16 * 9 * CH; idx += 512) {
        int k  = idx / (9 * CH);
        int r  = idx - k * 9 * CH;
        int ij = r >> 7;
        int c  = r & 127;
        w1s[idx] = w1[(k * CH + c) * 9 + ij];
    }
    if (tid < 16) b1s[tid] = b1[tid];
    __syncthreads();

    int warp = tid >> 5, lane = tid & 31;
    int kpa = blockIdx.x * 32 + warp * 2;
    int kpb = kpa + 1;

    float kxa = kpts[(size_t)kpa * 2 + 0], kya = kpts[(size_t)kpa * 2 + 1];
    float kxb = kpts[(size_t)kpb * 2 + 0], kyb = kpts[(size_t)kpb * 2 + 1];
    float kwxa = (kxa * 0.5f + 0.5f) * (float)(WW - 1);
    float kwya = (kya * 0.5f + 0.5f) * (float)(HH - 1);
    float kwxb = (kxb * 0.5f + 0.5f) * (float)(WW - 1);
    float kwyb = (kyb * 0.5f + 0.5f) * (float)(HH - 1);
    int cxa = min(max((int)((float)((int)kwxa) - 0.5f), 0), WW - 1 - KSZ);
    int cya = min(max((int)((float)((int)kwya) - 0.5f), 0), HH - 1 - KSZ);
    int cxb = min(max((int)((float)((int)kwxb) - 0.5f), 0), WW - 1 - KSZ);
    int cyb = min(max((int)((float)((int)kwyb) - 0.5f), 0), HH - 1 - KSZ);

    const float* basea = g_xT + (size_t)(kpa / NK) * HWSZ * CH + lane * 4;
    const float* baseb = g_xT + (size_t)(kpb / NK) * HWSZ * CH + lane * 4;

    float4 pa[9], pb[9];
    #pragma unroll
    for (int iy = 0; iy < 3; iy++)
        #pragma unroll
        for (int ix = 0; ix < 3; ix++) {
            pa[iy * 3 + ix] = *(const float4*)(basea + ((size_t)(cya + iy) * WW + (cxa + ix)) * CH);
            pb[iy * 3 + ix] = *(const float4*)(baseb + ((size_t)(cyb + iy) * WW + (cxb + ix)) * CH);
        }

    float acc_a[16], acc_b[16];
    #pragma unroll
    for (int k = 0; k < 16; k++) {
        float a = 0.f, b = 0.f;
        #pragma unroll
        for (int ij = 0; ij < 9; ij++) {
            float4 w = *(const float4*)&w1s[(k * 9 + ij) * CH + lane * 4];
            a = fmaf(pa[ij].x, w.x, a); a = fmaf(pa[ij].y, w.y, a);
            a = fmaf(pa[ij].z, w.z, a); a = fmaf(pa[ij].w, w.w, a);
            b = fmaf(pb[ij].x, w.x, b); b = fmaf(pb[ij].y, w.y, b);
            b = fmaf(pb[ij].z, w.z, b); b = fmaf(pb[ij].w, w.w, b);
        }
        acc_a[k] = a; acc_b[k] = b;
    }
    #pragma unroll
    for (int k = 0; k < 16; k++) {
        #pragma unroll
        for (int off = 16; off; off >>= 1) {
            acc_a[k] += __shfl_xor_sync(0xffffffffu, acc_a[k], off);
            acc_b[k] += __shfl_xor_sync(0xffffffffu, acc_b[k], off);
        }
    }

    int n = lane & 15;
    bool isB = lane >= 16;
    float s = b2[n];
    #pragma unroll
    for (int k = 0; k < 16; k++) {
        float v = (isB ? acc_b[k] : acc_a[k]) + b1s[k];
        s = fmaf(fmaxf(v, 0.f), w2[n * 16 + k], s);
    }
    s = fminf(fmaxf(s, -MAXOFF), MAXOFF);

    float oy = __shfl_sync(0xffffffffu, s, (lane & 7) + 8 + (lane & 16));
    if ((lane & 15) < 8) {
        int kp   = isB ? kpb : kpa;
        float kwx = isB ? kwxb : kwxa;
        float kwy = isB ? kwyb : kwya;
        g_pos[(size_t)kp * NPOS + (lane & 7)] = make_float2(kwx + s, kwy + oy);
    }
}

// ---------------- K2b: warp-per-sample bilinear gather -> feats hi/lo -----------
__global__ __launch_bounds__(256) void k_bil() {
    int s = blockIdx.x * 8 + (threadIdx.x >> 5);
    int lane = threadIdx.x & 31;
    int kp = s >> 3;
    int b  = kp / NK;

    float2 pos = g_pos[s];
    float px = pos.x, py = pos.y;
    float x0f = floorf(px), y0f = floorf(py);
    float wx = px - x0f, wy = py - y0f;
    int ix0 = (int)x0f, iy0 = (int)y0f;
    bool xin0 = (x0f >= 0.f) & (x0f <= (float)(WW - 1));
    bool xin1 = (x0f + 1.f >= 0.f) & (x0f + 1.f <= (float)(WW - 1));
    bool yin0 = (y0f >= 0.f) & (y0f <= (float)(HH - 1));
    bool yin1 = (y0f + 1.f >= 0.f) & (y0f + 1.f <= (float)(HH - 1));
    int cx0 = min(max(ix0, 0), WW - 1),     cx1 = min(max(ix0 + 1, 0), WW - 1);
    int cy0 = min(max(iy0, 0), HH - 1),     cy1 = min(max(iy0 + 1, 0), HH - 1);

    const float* base = g_xT + (size_t)b * HWSZ * CH + lane * 4;
    float4 v00 = make_float4(0, 0, 0, 0), v10 = v00, v01 = v00, v11 = v00;
    if (xin0 & yin0) v00 = *(const float4*)(base + ((size_t)cy0 * WW + cx0) * CH);
    if (xin1 & yin0) v10 = *(const float4*)(base + ((size_t)cy0 * WW + cx1) * CH);
    if (xin0 & yin1) v01 = *(const float4*)(base + ((size_t)cy1 * WW + cx0) * CH);
    if (xin1 & yin1) v11 = *(const float4*)(base + ((size_t)cy1 * WW + cx1) * CH);

    float w00 = (1.f - wx) * (1.f - wy), w10 = wx * (1.f - wy);
    float w01 = (1.f - wx) * wy,         w11 = wx * wy;
    float f0 = v00.x * w00 + v10.x * w10 + v01.x * w01 + v11.x * w11;
    float f1 = v00.y * w00 + v10.y * w10 + v01.y * w01 + v11.y * w11;
    float f2 = v00.z * w00 + v10.z * w10 + v01.z * w01 + v11.z * w11;
    float f3 = v00.w * w00 + v10.w * w10 + v01.w * w01 + v11.w * w11;

    float h0 = __bfloat162float(__float2bfloat16(f0));
    float h1 = __bfloat162float(__float2bfloat16(f1));
    float h2 = __bfloat162float(__float2bfloat16(f2));
    float h3 = __bfloat162float(__float2bfloat16(f3));

    size_t o = (size_t)s * CH + lane * 4;
    *(uint2*)(g_fhi + o) = make_uint2(pack2bf(f0, f1), pack2bf(f2, f3));
    *(uint2*)(g_flo + o) = make_uint2(pack2bf(f0 - h0, f1 - h1), pack2bf(f2 - h2, f3 - h3));
}

// ---------------- K3: split-K fused GEMM, M=64, d-half per block ----------------
// Block (tile, nb): G_half = selu(F_g @ sfw[64nb:+64]^T) entirely in registers,
// D2_partial += G_half @ aggT[:, c' in half]. 64KB smem -> 3 blocks/SM, grid 500.
// SMEM: F (hi 16K + lo 16K) + B-slot (hi 16K + lo 16K); B-slot = sfw-half (SW_OFF,
// 64x256B) alternating with agg-half (SW8_OFF, 128x128B).
#define OF4_F_HI  0
#define OF4_F_LO  (16*1024)
#define OF4_B_HI  (32*1024)
#define OF4_B_LO  (48*1024)
#define SMEM_FUSED (64*1024)

// stage 64-row x 16-chunk tile (256B rows), 128 threads
__device__ __forceinline__ void stage16(uint32_t dst_sb, const __nv_bfloat16* src,
                                        int row_stride, int tid) {
    #pragma unroll
    for (int it = tid; it < 1024; it += 128) {
        int row = it >> 4, ch = it & 15;
        CP_ASYNC16(dst_sb + SW_OFF(row, ch),
                   (const void*)(src + (size_t)row * row_stride + ch * 8));
    }
}
// stage 128-row x 8-chunk tile (128B rows), 128 threads
__device__ __forceinline__ void stage8(uint32_t dst_sb, const __nv_bfloat16* src,
                                       int row_stride, int tid) {
    #pragma unroll
    for (int it = tid; it < 1024; it += 128) {
        int row = it >> 3, ch = it & 7;
        CP_ASYNC16(dst_sb + SW8_OFF(row, ch),
                   (const void*)(src + (size_t)row * row_stride + ch * 8));
    }
}

__global__ __launch_bounds__(128, 3) void k_fused() {
    extern __shared__ __align__(16) char smem[];
    int tid = threadIdx.x;
    int wid = tid >> 5, lane = tid & 31;
    int kp0 = blockIdx.x * 64;
    int nb  = blockIdx.y;               // d-half index
    int m0w = wid * 16;

    uint32_t sb = smem_u32(smem);
    const __nv_bfloat16* sfw_h = g_sfw_hi + 64 * nb * CH;
    const __nv_bfloat16* sfw_l = g_sfw_lo + 64 * nb * CH;

    // prologue: F_0 (group), sfw-half (group)
    stage16(sb + OF4_F_HI, g_fhi + ((size_t)kp0 * NPOS + 0) * CH, NPOS * CH, tid);
    stage16(sb + OF4_F_LO, g_flo + ((size_t)kp0 * NPOS + 0) * CH, NPOS * CH, tid);
    CP_COMMIT();
    stage16(sb + OF4_B_HI, sfw_h, CH, tid);
    stage16(sb + OF4_B_LO, sfw_l, CH, tid);
    CP_COMMIT();

    int a_row = m0w + (lane & 15);
    int a_chA = (lane >> 4);
    int b_rowi = (lane & 7) + ((lane >> 4) << 3);
    int b_chA = (lane >> 3) & 1;

    float d2[16][4];
    #pragma unroll
    for (int n = 0; n < 16; n++)
        #pragma unroll
        for (int j = 0; j < 4; j++) d2[n][j] = 0.f;

    for (int g = 0; g < NPOS; g++) {
        CP_WAIT(0);
        __syncthreads();

        // ---- MMA1: D1 = F_g @ sfw_half^T (N=64, K=128, 3-term split) ----
        float d1[8][4];
        #pragma unroll
        for (int n = 0; n < 8; n++)
            #pragma unroll
            for (int j = 0; j < 4; j++) d1[n][j] = 0.f;

        #pragma unroll
        for (int kt = 0; kt < 8; kt++) {
            uint32_t ah[4], al[4];
            ldsm4(ah, sb + OF4_F_HI + SW_OFF(a_row, 2 * kt + a_chA));
            ldsm4(al, sb + OF4_F_LO + SW_OFF(a_row, 2 * kt + a_chA));
            #pragma unroll
            for (int ntp = 0; ntp < 4; ntp++) {
                uint32_t bh[4], bl[4];
                int brow = 16 * ntp + b_rowi;
                ldsm4(bh, sb + OF4_B_HI + SW_OFF(brow, 2 * kt + b_chA));
                ldsm4(bl, sb + OF4_B_LO + SW_OFF(brow, 2 * kt + b_chA));
                mma16816(d1[2 * ntp],     ah, bh);
                mma16816(d1[2 * ntp],     ah, bl);
                mma16816(d1[2 * ntp],     al, bh);
                mma16816(d1[2 * ntp + 1], ah, bh + 2);
                mma16816(d1[2 * ntp + 1], ah, bl + 2);
                mma16816(d1[2 * ntp + 1], al, bh + 2);
            }
        }
        __syncthreads();   // F_g and B-slot(sfw) free

        // stream agg-half (group A), F_{g+1} (group B)
        stage8(sb + OF4_B_HI, g_agg_hi + (size_t)g * CH * CH + 64 * nb, CH, tid);
        stage8(sb + OF4_B_LO, g_agg_lo + (size_t)g * CH * CH + 64 * nb, CH, tid);
        CP_COMMIT();   // A
        if (g + 1 < NPOS) {
            stage16(sb + OF4_F_HI, g_fhi + ((size_t)kp0 * NPOS + g + 1) * CH, NPOS * CH, tid);
            stage16(sb + OF4_F_LO, g_flo + ((size_t)kp0 * NPOS + g + 1) * CH, NPOS * CH, tid);
        }
        CP_COMMIT();   // B (possibly empty)

        // ---- SELU + register re-layout: D1 tiles -> A fragments (local K=64) ----
        const float SC = 1.0507009873554805f, AL = 1.6732632423543772f;
        uint32_t a2h[4][4], a2l[4][4];
        #pragma unroll
        for (int kt2 = 0; kt2 < 4; kt2++) {
            float z[8];
            #pragma unroll
            for (int j = 0; j < 4; j++) {
                float v0 = d1[2 * kt2][j];
                float v1 = d1[2 * kt2 + 1][j];
                z[j]     = (v0 > 0.f) ? SC * v0 : SC * AL * expm1f(v0);
                z[4 + j] = (v1 > 0.f) ? SC * v1 : SC * AL * expm1f(v1);
            }
            float h0 = __bfloat162float(__float2bfloat16(z[0]));
            float h1 = __bfloat162float(__float2bfloat16(z[1]));
            float h2 = __bfloat162float(__float2bfloat16(z[2]));
            float h3 = __bfloat162float(__float2bfloat16(z[3]));
            float h4 = __bfloat162float(__float2bfloat16(z[4]));
            float h5 = __bfloat162float(__float2bfloat16(z[5]));
            float h6 = __bfloat162float(__float2bfloat16(z[6]));
            float h7 = __bfloat162float(__float2bfloat16(z[7]));
            a2h[kt2][0] = pack2bf(z[0], z[1]);
            a2h[kt2][1] = pack2bf(z[2], z[3]);
            a2h[kt2][2] = pack2bf(z[4], z[5]);
            a2h[kt2][3] = pack2bf(z[6], z[7]);
            a2l[kt2][0] = pack2bf(z[0] - h0, z[1] - h1);
            a2l[kt2][1] = pack2bf(z[2] - h2, z[3] - h3);
            a2l[kt2][2] = pack2bf(z[4] - h4, z[5] - h5);
            a2l[kt2][3] = pack2bf(z[6] - h6, z[7] - h7);
        }

        CP_WAIT(1);        // agg-half (A) landed; F_{g+1} (B) may fly
        __syncthreads();

        // ---- MMA2: D2 += G_half @ aggT_half (N=128, local K=64, A in regs) ----
        #pragma unroll
        for (int ktl = 0; ktl < 4; ktl++) {
            #pragma unroll
            for (int ntp = 0; ntp < 8; ntp++) {
                uint32_t bh[4], bl[4];
                int brow = 16 * ntp + b_rowi;
                ldsm4(bh, sb + OF4_B_HI + SW8_OFF(brow, 2 * ktl + b_chA));
                ldsm4(bl, sb + OF4_B_LO + SW8_OFF(brow, 2 * ktl + b_chA));
                mma16816(d2[2 * ntp],     a2h[ktl], bh);
                mma16816(d2[2 * ntp],     a2h[ktl], bl);
                mma16816(d2[2 * ntp],     a2l[ktl], bh);
                mma16816(d2[2 * ntp + 1], a2h[ktl], bh + 2);
                mma16816(d2[2 * ntp + 1], a2h[ktl], bl + 2);
                mma16816(d2[2 * ntp + 1], a2l[ktl], bh + 2);
            }
        }
        __syncthreads();   // B-slot(agg) free

        // refill sfw-half for next MMA1 (group C; waited at loop top with B)
        if (g + 1 < NPOS) {
            stage16(sb + OF4_B_HI, sfw_h, CH, tid);
            stage16(sb + OF4_B_LO, sfw_l, CH, tid);
            CP_COMMIT();
        }
    }

    // ---- write partial D2 (no norm here) ----
    {
        int r0 = m0w + (lane >> 2);
        int t = lane & 3;
        float* rowA = g_part[nb] + (size_t)(kp0 + r0) * CH;
        float* rowB = g_part[nb] + (size_t)(kp0 + r0 + 8) * CH;
        #pragma unroll
        for (int n = 0; n < 16; n++) {
            int col = n * 8 + 2 * t;
            *(float2*)(rowA + col) = make_float2(d2[n][0], d2[n][1]);
            *(float2*)(rowB + col) = make_float2(d2[n][2], d2[n][3]);
        }
    }
}

// ---------------- K4: sum partials + L2 normalize --------------------------------
__global__ __launch_bounds__(256) void k_norm(float* __restrict__ out) {
    int r = blockIdx.x * 8 + (threadIdx.x >> 5);
    int lane = threadIdx.x & 31;
    size_t o = (size_t)r * CH + lane * 4;
    float4 v0 = *(const float4*)(g_part[0] + o);
    float4 v1 = *(const float4*)(g_part[1] + o);
    float4 s = make_float4(v0.x + v1.x, v0.y + v1.y, v0.z + v1.z, v0.w + v1.w);
    float ss = fmaf(s.x, s.x, fmaf(s.y, s.y, fmaf(s.z, s.z, s.w * s.w)));
    #pragma unroll
    for (int off = 16; off; off >>= 1) ss += __shfl_xor_sync(0xffffffffu, ss, off);
    float inv = 1.f / fmaxf(sqrtf(ss), 1e-12f);
    *(float4*)(out + o) = make_float4(s.x * inv, s.y * inv, s.z * inv, s.w * inv);
}

// ---------------- launch ---------------------------------------------------------
extern "C" void kernel_launch(void* const* d_in, const int* in_sizes, int n_in,
                              void* d_out, int out_size) {
    (void)in_sizes; (void)n_in; (void)out_size;
    const float* x    = (const float*)d_in[0];
    const float* kpts = (const float*)d_in[1];
    const float* w1   = (const float*)d_in[2];
    const float* b1   = (const float*)d_in[3];
    const float* w2   = (const float*)d_in[4];
    const float* b2   = (const float*)d_in[5];
    const float* sfw  = (const float*)d_in[6];
    const float* aggw = (const float*)d_in[7];
    float* out = (float*)d_out;

    const int smemOff = 16 * 9 * CH * sizeof(float);   // 73.7 KB
    cudaFuncSetAttribute(k_off,   cudaFuncAttributeMaxDynamicSharedMemorySize, smemOff);
    cudaFuncSetAttribute(k_fused, cudaFuncAttributeMaxDynamicSharedMemorySize, SMEM_FUSED);

    k_transpose<<<dim3(HWSZ / 32, CH / 32, BB), dim3(32, 8)>>>(x);
    k_prep<<<dim3(4, 4, NPOS + 1), dim3(32, 8)>>>(aggw, sfw);
    k_off<<<NKP_TOT / 32, 512, smemOff>>>(kpts, w1, b1, w2, b2);
    k_bil<<<MROWS / 8, 256>>>();
    k_fused<<<dim3(NKP_TOT / 64, 2), 128, SMEM_FUSED>>>();
    k_norm<<<NKP_TOT / 8, 256>>>(out);
}

// round 17
// speedup vs baseline: 1.0619x; 1.0619x over previous
#include <cuda_runtime.h>
#include <cuda_bf16.h>
#include <math.h>
#include <cstdint>

#define BB   4
#define CH   128
#define HH   240
#define WW   320
#define NK   4000
#define NPOS 8
#define KSZ  3
#define HWSZ (HH*WW)
#define MAXOFF 80.0f

#define NKP_TOT (BB*NK)          // 16000
#define MROWS   (NKP_TOT*NPOS)   // 128000

// ---------------- scratch (static device globals; no runtime alloc) ------------
__device__ __align__(16) float g_xT[(size_t)BB*HWSZ*CH];        // NHWC
__device__ __align__(16) float2 g_pos[(size_t)MROWS];           // sample positions (px,py)
__device__ __align__(256) __nv_bfloat16 g_fhi[(size_t)MROWS*CH];
__device__ __align__(256) __nv_bfloat16 g_flo[(size_t)MROWS*CH];
__device__ __align__(256) __nv_bfloat16 g_sfw_hi[CH*CH];        // [d][c]
__device__ __align__(256) __nv_bfloat16 g_sfw_lo[CH*CH];
__device__ __align__(256) __nv_bfloat16 g_agg_hi[NPOS*CH*CH];   // [p][d][c]
__device__ __align__(256) __nv_bfloat16 g_agg_lo[NPOS*CH*CH];

// ================= warp-MMA helpers (HMMA path, works on plain sm_103) ==========
__device__ __forceinline__ uint32_t smem_u32(const void* p) {
    return (uint32_t)__cvta_generic_to_shared(p);
}
__device__ __forceinline__ void ldsm4(uint32_t r[4], uint32_t addr) {
    asm volatile("ldmatrix.sync.aligned.m8n8.x4.shared.b16 {%0,%1,%2,%3}, [%4];"
                 : "=r"(r[0]), "=r"(r[1]), "=r"(r[2]), "=r"(r[3]) : "r"(addr));
}
__device__ __forceinline__ void mma16816(float d[4], const uint32_t a[4], const uint32_t b[2]) {
    asm volatile("mma.sync.aligned.m16n8k16.row.col.f32.bf16.bf16.f32 "
                 "{%0,%1,%2,%3}, {%4,%5,%6,%7}, {%8,%9}, {%0,%1,%2,%3};"
                 : "+f"(d[0]), "+f"(d[1]), "+f"(d[2]), "+f"(d[3])
                 : "r"(a[0]), "r"(a[1]), "r"(a[2]), "r"(a[3]), "r"(b[0]), "r"(b[1]));
}
__device__ __forceinline__ uint32_t pack2bf(float a, float b) {
    __nv_bfloat162 t = __floats2bfloat162_rn(a, b);
    return *(uint32_t*)&t;
}
// 16B-chunk XOR swizzle for a tile with 256B rows (16 chunks/row)
#define SW_OFF(row, chunk) ((uint32_t)(row) * 256u + ((uint32_t)((chunk) ^ ((row) & 7)) << 4))

#define CP_ASYNC16(dst, src) \
    asm volatile("cp.async.cg.shared.global [%0], [%1], 16;" :: "r"(dst), "l"(src))
#define CP_COMMIT() asm volatile("cp.async.commit_group;" ::: "memory")
#define CP_WAIT(n)  asm volatile("cp.async.wait_group %0;" :: "n"(n) : "memory")

// ---------------- K1: NCHW -> NHWC transpose ------------------------------------
__global__ void k_transpose(const float* __restrict__ x) {
    __shared__ float tile[32][33];
    int b  = blockIdx.z;
    int c0 = blockIdx.y * 32;
    int hw0 = blockIdx.x * 32;
    int tx = threadIdx.x, ty = threadIdx.y;     // 32 x 8
    const float* xb = x + (size_t)b * CH * HWSZ;
    #pragma unroll
    for (int i = ty; i < 32; i += 8)
        tile[i][tx] = xb[(size_t)(c0 + i) * HWSZ + hw0 + tx];
    __syncthreads();
    float* ob = g_xT + (size_t)b * HWSZ * CH;
    #pragma unroll
    for (int i = ty; i < 32; i += 8)
        ob[(size_t)(hw0 + i) * CH + c0 + tx] = tile[tx][i];
}

// ---------------- merged prep: agg transpose-split (z<NPOS) + sfw split (z==NPOS)
__global__ void k_prep(const float* __restrict__ agg, const float* __restrict__ sfw) {
    __shared__ float t[32][33];
    int p  = blockIdx.z;
    int tx = threadIdx.x, ty = threadIdx.y;     // 32 x 8
    if (p == NPOS) {
        int c0 = blockIdx.x * 32;
        int d0 = blockIdx.y * 32;
        #pragma unroll
        for (int i = ty; i < 32; i += 8) {
            int idx = (d0 + i) * CH + c0 + tx;
            float v = sfw[idx];
            __nv_bfloat16 h = __float2bfloat16(v);
            g_sfw_hi[idx] = h;
            g_sfw_lo[idx] = __float2bfloat16(v - __bfloat162float(h));
        }
        return;
    }
    int c0 = blockIdx.x * 32;
    int d0 = blockIdx.y * 32;
    const float* src = agg + (size_t)p * CH * CH;
    #pragma unroll
    for (int i = ty; i < 32; i += 8)
        t[i][tx] = src[(size_t)(c0 + i) * CH + d0 + tx];
    __syncthreads();
    #pragma unroll
    for (int i = ty; i < 32; i += 8) {
        float v = t[tx][i];
        __nv_bfloat16 h = __float2bfloat16(v);
        size_t oi = (size_t)p * CH * CH + (size_t)(d0 + i) * CH + c0 + tx;
        g_agg_hi[oi] = h;
        g_agg_lo[oi] = __float2bfloat16(v - __bfloat162float(h));
    }
}

// ---------------- K2a: 2-kp-per-warp offset MLP, 512 thr = 32 kp/block ----------
__global__ __launch_bounds__(512) void k_off(
        const float* __restrict__ kpts,
        const float* __restrict__ w1, const float* __restrict__ b1,
        const float* __restrict__ w2, const float* __restrict__ b2) {
    extern __shared__ float w1s[];            // [16][9][128]
    __shared__ float b1s[16];

    int tid = threadIdx.x;
    for (int idx = tid; idx < 16 * 9 * CH; idx += 512) {
        int k  = idx / (9 * CH);
        int r  = idx - k * 9 * CH;
        int ij = r >> 7;
        int c  = r & 127;
        w1s[idx] = w1[(k * CH + c) * 9 + ij];
    }
    if (tid < 16) b1s[tid] = b1[tid];
    __syncthreads();

    int warp = tid >> 5, lane = tid & 31;
    int kpa = blockIdx.x * 32 + warp * 2;
    int kpb = kpa + 1;

    float kxa = kpts[(size_t)kpa * 2 + 0], kya = kpts[(size_t)kpa * 2 + 1];
    float kxb = kpts[(size_t)kpb * 2 + 0], kyb = kpts[(size_t)kpb * 2 + 1];
    float kwxa = (kxa * 0.5f + 0.5f) * (float)(WW - 1);
    float kwya = (kya * 0.5f + 0.5f) * (float)(HH - 1);
    float kwxb = (kxb * 0.5f + 0.5f) * (float)(WW - 1);
    float kwyb = (kyb * 0.5f + 0.5f) * (float)(HH - 1);
    int cxa = min(max((int)((float)((int)kwxa) - 0.5f), 0), WW - 1 - KSZ);
    int cya = min(max((int)((float)((int)kwya) - 0.5f), 0), HH - 1 - KSZ);
    int cxb = min(max((int)((float)((int)kwxb) - 0.5f), 0), WW - 1 - KSZ);
    int cyb = min(max((int)((float)((int)kwyb) - 0.5f), 0), HH - 1 - KSZ);

    const float* basea = g_xT + (size_t)(kpa / NK) * HWSZ * CH + lane * 4;
    const float* baseb = g_xT + (size_t)(kpb / NK) * HWSZ * CH + lane * 4;

    float4 pa[9], pb[9];
    #pragma unroll
    for (int iy = 0; iy < 3; iy++)
        #pragma unroll
        for (int ix = 0; ix < 3; ix++) {
            pa[iy * 3 + ix] = *(const float4*)(basea + ((size_t)(cya + iy) * WW + (cxa + ix)) * CH);
            pb[iy * 3 + ix] = *(const float4*)(baseb + ((size_t)(cyb + iy) * WW + (cxb + ix)) * CH);
        }

    float acc_a[16], acc_b[16];
    #pragma unroll
    for (int k = 0; k < 16; k++) {
        float a = 0.f, b = 0.f;
        #pragma unroll
        for (int ij = 0; ij < 9; ij++) {
            float4 w = *(const float4*)&w1s[(k * 9 + ij) * CH + lane * 4];
            a = fmaf(pa[ij].x, w.x, a); a = fmaf(pa[ij].y, w.y, a);
            a = fmaf(pa[ij].z, w.z, a); a = fmaf(pa[ij].w, w.w, a);
            b = fmaf(pb[ij].x, w.x, b); b = fmaf(pb[ij].y, w.y, b);
            b = fmaf(pb[ij].z, w.z, b); b = fmaf(pb[ij].w, w.w, b);
        }
        acc_a[k] = a; acc_b[k] = b;
    }
    #pragma unroll
    for (int k = 0; k < 16; k++) {
        #pragma unroll
        for (int off = 16; off; off >>= 1) {
            acc_a[k] += __shfl_xor_sync(0xffffffffu, acc_a[k], off);
            acc_b[k] += __shfl_xor_sync(0xffffffffu, acc_b[k], off);
        }
    }

    int n = lane & 15;
    bool isB = lane >= 16;
    float s = b2[n];
    #pragma unroll
    for (int k = 0; k < 16; k++) {
        float v = (isB ? acc_b[k] : acc_a[k]) + b1s[k];
        s = fmaf(fmaxf(v, 0.f), w2[n * 16 + k], s);
    }
    s = fminf(fmaxf(s, -MAXOFF), MAXOFF);

    float oy = __shfl_sync(0xffffffffu, s, (lane & 7) + 8 + (lane & 16));
    if ((lane & 15) < 8) {
        int kp   = isB ? kpb : kpa;
        float kwx = isB ? kwxb : kwxa;
        float kwy = isB ? kwyb : kwya;
        g_pos[(size_t)kp * NPOS + (lane & 7)] = make_float2(kwx + s, kwy + oy);
    }
}

// ---------------- K2b: warp-per-sample bilinear gather -> feats hi/lo -----------
__global__ __launch_bounds__(256) void k_bil() {
    int s = blockIdx.x * 8 + (threadIdx.x >> 5);
    int lane = threadIdx.x & 31;
    int kp = s >> 3;
    int b  = kp / NK;

    float2 pos = g_pos[s];
    float px = pos.x, py = pos.y;
    float x0f = floorf(px), y0f = floorf(py);
    float wx = px - x0f, wy = py - y0f;
    int ix0 = (int)x0f, iy0 = (int)y0f;
    bool xin0 = (x0f >= 0.f) & (x0f <= (float)(WW - 1));
    bool xin1 = (x0f + 1.f >= 0.f) & (x0f + 1.f <= (float)(WW - 1));
    bool yin0 = (y0f >= 0.f) & (y0f <= (float)(HH - 1));
    bool yin1 = (y0f + 1.f >= 0.f) & (y0f + 1.f <= (float)(HH - 1));
    int cx0 = min(max(ix0, 0), WW - 1),     cx1 = min(max(ix0 + 1, 0), WW - 1);
    int cy0 = min(max(iy0, 0), HH - 1),     cy1 = min(max(iy0 + 1, 0), HH - 1);

    const float* base = g_xT + (size_t)b * HWSZ * CH + lane * 4;
    float4 v00 = make_float4(0, 0, 0, 0), v10 = v00, v01 = v00, v11 = v00;
    if (xin0 & yin0) v00 = *(const float4*)(base + ((size_t)cy0 * WW + cx0) * CH);
    if (xin1 & yin0) v10 = *(const float4*)(base + ((size_t)cy0 * WW + cx1) * CH);
    if (xin0 & yin1) v01 = *(const float4*)(base + ((size_t)cy1 * WW + cx0) * CH);
    if (xin1 & yin1) v11 = *(const float4*)(base + ((size_t)cy1 * WW + cx1) * CH);

    float w00 = (1.f - wx) * (1.f - wy), w10 = wx * (1.f - wy);
    float w01 = (1.f - wx) * wy,         w11 = wx * wy;
    float f0 = v00.x * w00 + v10.x * w10 + v01.x * w01 + v11.x * w11;
    float f1 = v00.y * w00 + v10.y * w10 + v01.y * w01 + v11.y * w11;
    float f2 = v00.z * w00 + v10.z * w10 + v01.z * w01 + v11.z * w11;
    float f3 = v00.w * w00 + v10.w * w10 + v01.w * w01 + v11.w * w11;

    float h0 = __bfloat162float(__float2bfloat16(f0));
    float h1 = __bfloat162float(__float2bfloat16(f1));
    float h2 = __bfloat162float(__float2bfloat16(f2));
    float h3 = __bfloat162float(__float2bfloat16(f3));

    size_t o = (size_t)s * CH + lane * 4;
    *(uint2*)(g_fhi + o) = make_uint2(pack2bf(f0, f1), pack2bf(f2, f3));
    *(uint2*)(g_flo + o) = make_uint2(pack2bf(f0 - h0, f1 - h1), pack2bf(f2 - h2, f3 - h3));
}

// ---------------- K3: fused GEMM, M=128 tile, 512 thr, double-buffered B --------
// Warp (rw = wid&7, nh = wid>>3): rows 16rw..+15, N-half 64nh..+63.
// SMEM: F/G 64K | B0 (sfw) 64K | B1 (agg) 64K = 192K -> 1 block/SM, 16 warps.
// sfw->B0 prefetched during SELU+MMA2; agg->B1 during next MMA1; only F exposed.
#define OF5_F_HI  0
#define OF5_F_LO  (32*1024)
#define OF5_B0_HI (64*1024)
#define OF5_B0_LO (96*1024)
#define OF5_B1_HI (128*1024)
#define OF5_B1_LO (160*1024)
#define SMEM_FUSED (192*1024)

// stage a [128 rows x 128 bf16] tile (2048 chunks) with 512 threads
__device__ __forceinline__ void stage128(uint32_t dst_sb, const __nv_bfloat16* src,
                                         int row_stride, int tid) {
    #pragma unroll
    for (int it = tid; it < 2048; it += 512) {
        int row = it >> 4, ch = it & 15;
        CP_ASYNC16(dst_sb + SW_OFF(row, ch),
                   (const void*)(src + (size_t)row * row_stride + ch * 8));
    }
}

__global__ __launch_bounds__(512, 1) void k_fused(float* __restrict__ out) {
    extern __shared__ __align__(16) char smem[];
    int tid = threadIdx.x;
    int wid = tid >> 5, lane = tid & 31;
    int rw = wid & 7, nh = wid >> 3;
    int kp0 = blockIdx.x * 128;
    int m0w = rw * 16;

    uint32_t sb = smem_u32(smem);

    // prologue: F_0 + agg_0 (group Q), sfw (group P)
    stage128(sb + OF5_F_HI, g_fhi + ((size_t)kp0 * NPOS + 0) * CH, NPOS * CH, tid);
    stage128(sb + OF5_F_LO, g_flo + ((size_t)kp0 * NPOS + 0) * CH, NPOS * CH, tid);
    stage128(sb + OF5_B1_HI, g_agg_hi, CH, tid);
    stage128(sb + OF5_B1_LO, g_agg_lo, CH, tid);
    CP_COMMIT();
    stage128(sb + OF5_B0_HI, g_sfw_hi, CH, tid);
    stage128(sb + OF5_B0_LO, g_sfw_lo, CH, tid);
    CP_COMMIT();

    int a_row = m0w + (lane & 15);
    int a_chA = (lane >> 4);
    int b_rowi = (lane & 7) + ((lane >> 4) << 3);
    int b_chA = (lane >> 3) & 1;
    int b_base = 64 * nh;               // this warp's N-half in B tiles

    float d2[8][4];
    #pragma unroll
    for (int n = 0; n < 8; n++)
        #pragma unroll
        for (int j = 0; j < 4; j++) d2[n][j] = 0.f;

    for (int g = 0; g < NPOS; g++) {
        // F_g (+agg_g) and sfw must be complete
        CP_WAIT(0);
        __syncthreads();

        // ---- MMA1: D1 = feats_g @ sfw^T, this warp's N-half (3-term split) ----
        float d1[8][4];
        #pragma unroll
        for (int n = 0; n < 8; n++)
            #pragma unroll
            for (int j = 0; j < 4; j++) d1[n][j] = 0.f;

        #pragma unroll
        for (int kt = 0; kt < 8; kt++) {
            uint32_t ah[4], al[4];
            ldsm4(ah, sb + OF5_F_HI + SW_OFF(a_row, 2 * kt + a_chA));
            ldsm4(al, sb + OF5_F_LO + SW_OFF(a_row, 2 * kt + a_chA));
            #pragma unroll
            for (int ntp = 0; ntp < 4; ntp++) {
                uint32_t bh[4], bl[4];
                int brow = b_base + 16 * ntp + b_rowi;
                ldsm4(bh, sb + OF5_B0_HI + SW_OFF(brow, 2 * kt + b_chA));
                ldsm4(bl, sb + OF5_B0_LO + SW_OFF(brow, 2 * kt + b_chA));
                mma16816(d1[2 * ntp],     ah, bh);
                mma16816(d1[2 * ntp],     ah, bl);
                mma16816(d1[2 * ntp],     al, bh);
                mma16816(d1[2 * ntp + 1], ah, bh + 2);
                mma16816(d1[2 * ntp + 1], ah, bl + 2);
                mma16816(d1[2 * ntp + 1], al, bh + 2);
            }
        }
        __syncthreads();   // all warps done with F_g (A) and B0 (sfw)

        // prefetch sfw for next iteration (overlaps SELU + MMA2)
        if (g + 1 < NPOS) {
            stage128(sb + OF5_B0_HI, g_sfw_hi, CH, tid);
            stage128(sb + OF5_B0_LO, g_sfw_lo, CH, tid);
            CP_COMMIT();
        }

        // ---- SELU -> bf16 hi/lo -> STS into F buffer (now the G tile) ----
        const float SC = 1.0507009873554805f, AL = 1.6732632423543772f;
        {
            int r0 = m0w + (lane >> 2);
            uint32_t off4 = (uint32_t)(lane & 3) * 4u;
            #pragma unroll
            for (int n = 0; n < 8; n++) {
                float z0 = d1[n][0], z1 = d1[n][1], z2 = d1[n][2], z3 = d1[n][3];
                z0 = (z0 > 0.f) ? SC * z0 : SC * AL * expm1f(z0);
                z1 = (z1 > 0.f) ? SC * z1 : SC * AL * expm1f(z1);
                z2 = (z2 > 0.f) ? SC * z2 : SC * AL * expm1f(z2);
                z3 = (z3 > 0.f) ? SC * z3 : SC * AL * expm1f(z3);
                float h0 = __bfloat162float(__float2bfloat16(z0));
                float h1 = __bfloat162float(__float2bfloat16(z1));
                float h2 = __bfloat162float(__float2bfloat16(z2));
                float h3 = __bfloat162float(__float2bfloat16(z3));
                int chunk = 8 * nh + n;
                *(uint32_t*)(smem + OF5_F_HI + SW_OFF(r0,     chunk) + off4) = pack2bf(z0, z1);
                *(uint32_t*)(smem + OF5_F_LO + SW_OFF(r0,     chunk) + off4) = pack2bf(z0 - h0, z1 - h1);
                *(uint32_t*)(smem + OF5_F_HI + SW_OFF(r0 + 8, chunk) + off4) = pack2bf(z2, z3);
                *(uint32_t*)(smem + OF5_F_LO + SW_OFF(r0 + 8, chunk) + off4) = pack2bf(z2 - h2, z3 - h3);
            }
        }
        __syncthreads();   // G tile complete (agg_g was waited at loop top)

        // ---- MMA2: D2 += G @ agg_g^T, this warp's N-half ----
        #pragma unroll
        for (int kt = 0; kt < 8; kt++) {
            uint32_t ah[4], al[4];
            ldsm4(ah, sb + OF5_F_HI + SW_OFF(a_row, 2 * kt + a_chA));
            ldsm4(al, sb + OF5_F_LO + SW_OFF(a_row, 2 * kt + a_chA));
            #pragma unroll
            for (int ntp = 0; ntp < 4; ntp++) {
                uint32_t bh[4], bl[4];
                int brow = b_base + 16 * ntp + b_rowi;
                ldsm4(bh, sb + OF5_B1_HI + SW_OFF(brow, 2 * kt + b_chA));
                ldsm4(bl, sb + OF5_B1_LO + SW_OFF(brow, 2 * kt + b_chA));
                mma16816(d2[2 * ntp],     ah, bh);
                mma16816(d2[2 * ntp],     ah, bl);
                mma16816(d2[2 * ntp],     al, bh);
                mma16816(d2[2 * ntp + 1], ah, bh + 2);
                mma16816(d2[2 * ntp + 1], ah, bl + 2);
                mma16816(d2[2 * ntp + 1], al, bh + 2);
            }
        }
        __syncthreads();   // all warps done with G tile and B1 (agg_g)

        // prefetch F_{g+1} and agg_{g+1} (F exposed over backedge only)
        if (g + 1 < NPOS) {
            stage128(sb + OF5_F_HI, g_fhi + ((size_t)kp0 * NPOS + g + 1) * CH, NPOS * CH, tid);
            stage128(sb + OF5_F_LO, g_flo + ((size_t)kp0 * NPOS + g + 1) * CH, NPOS * CH, tid);
            stage128(sb + OF5_B1_HI, g_agg_hi + (size_t)(g + 1) * CH * CH, CH, tid);
            stage128(sb + OF5_B1_LO, g_agg_lo + (size_t)(g + 1) * CH * CH, CH, tid);
            CP_COMMIT();
        }
    }

    // ---- epilogue: cross-half row L2 norm + store ----
    float* nrm = (float*)(smem + OF5_B0_HI);   // [128][2] partial sums
    {
        float ssA = 0.f, ssB = 0.f;
        #pragma unroll
        for (int n = 0; n < 8; n++) {
            ssA = fmaf(d2[n][0], d2[n][0], fmaf(d2[n][1], d2[n][1], ssA));
            ssB = fmaf(d2[n][2], d2[n][2], fmaf(d2[n][3], d2[n][3], ssB));
        }
        ssA += __shfl_xor_sync(0xffffffffu, ssA, 1);
        ssA += __shfl_xor_sync(0xffffffffu, ssA, 2);
        ssB += __shfl_xor_sync(0xffffffffu, ssB, 1);
        ssB += __shfl_xor_sync(0xffffffffu, ssB, 2);
        int r0 = m0w + (lane >> 2);
        if ((lane & 3) == 0) {
            nrm[r0 * 2 + nh]       = ssA;
            nrm[(r0 + 8) * 2 + nh] = ssB;
        }
    }
    __syncthreads();

    {
        int r0 = m0w + (lane >> 2);
        float invA = 1.f / fmaxf(sqrtf(nrm[r0 * 2] + nrm[r0 * 2 + 1]), 1e-12f);
        float invB = 1.f / fmaxf(sqrtf(nrm[(r0 + 8) * 2] + nrm[(r0 + 8) * 2 + 1]), 1e-12f);
        int t = lane & 3;
        float* rowA = out + (size_t)(kp0 + r0) * CH + 64 * nh;
        float* rowB = out + (size_t)(kp0 + r0 + 8) * CH + 64 * nh;
        #pragma unroll
        for (int n = 0; n < 8; n++) {
            int col = n * 8 + 2 * t;
            *(float2*)(rowA + col) = make_float2(d2[n][0] * invA, d2[n][1] * invA);
            *(float2*)(rowB + col) = make_float2(d2[n][2] * invB, d2[n][3] * invB);
        }
    }
}

// ---------------- launch ---------------------------------------------------------
extern "C" void kernel_launch(void* const* d_in, const int* in_sizes, int n_in,
                              void* d_out, int out_size) {
    (void)in_sizes; (void)n_in; (void)out_size;
    const float* x    = (const float*)d_in[0];
    const float* kpts = (const float*)d_in[1];
    const float* w1   = (const float*)d_in[2];
    const float* b1   = (const float*)d_in[3];
    const float* w2   = (const float*)d_in[4];
    const float* b2   = (const float*)d_in[5];
    const float* sfw  = (const float*)d_in[6];
    const float* aggw = (const float*)d_in[7];
    float* out = (float*)d_out;

    const int smemOff = 16 * 9 * CH * sizeof(float);   // 73.7 KB
    cudaFuncSetAttribute(k_off,   cudaFuncAttributeMaxDynamicSharedMemorySize, smemOff);
    cudaFuncSetAttribute(k_fused, cudaFuncAttributeMaxDynamicSharedMemorySize, SMEM_FUSED);

    k_transpose<<<dim3(HWSZ / 32, CH / 32, BB), dim3(32, 8)>>>(x);
    k_prep<<<dim3(4, 4, NPOS + 1), dim3(32, 8)>>>(aggw, sfw);
    k_off<<<NKP_TOT / 32, 512, smemOff>>>(kpts, w1, b1, w2, b2);
    k_bil<<<MROWS / 8, 256>>>();
    k_fused<<<NKP_TOT / 128, 512, SMEM_FUSED>>>(out);
}